// round 12
// baseline (speedup 1.0000x reference)
#include <cuda_runtime.h>
#include <cuda_fp16.h>
#include <cstdint>

// ---------------------------------------------------------------------------
// SwinStyleAttention, fp16 mma.sync, fp32 accumulate. Persistent-weight kernel.
// B=8, C=128, H=W=256, WS=8, SS=4, HEADS=4, DH=32.
// 152 CTAs x 512 threads; two independent half-CTAs (named barriers), each
// half processes one 64-token window at a time. Weights resident in smem.
// ---------------------------------------------------------------------------

#define SCALE_F 0.17677669529663687f

#define WQ_OFF  0
#define WK_OFF  32768
#define WV_OFF  65536
#define WP_OFF  98304
#define HBASE   131072     // per-half: X/V 16KB, Q 16KB, K/O 16KB
#define HSTRIDE 49152
#define SMEM_TOTAL 229376

#define NCTA    152
#define WSTRIDE (NCTA * 2)

__device__ __align__(16) __half g_wh[4][16384];   // WqT, WkT, WvT, WprojT

__device__ __forceinline__ uint32_t s2u(const void* p) {
    uint32_t a;
    asm("{ .reg .u64 t; cvta.to.shared.u64 t, %1; cvt.u32.u64 %0, t; }" : "=r"(a) : "l"(p));
    return a;
}
// (row, 16B-chunk) in a 256B-row fp16 tile, XOR-swizzled
__device__ __forceinline__ uint32_t xoff(int row, int chunk) {
    return (uint32_t)(row * 256 + ((chunk ^ (row & 7)) << 4));
}
__device__ __forceinline__ void ldm4(uint32_t r[4], uint32_t addr) {
    asm volatile("ldmatrix.sync.aligned.m8n8.x4.shared.b16 {%0,%1,%2,%3}, [%4];"
                 : "=r"(r[0]), "=r"(r[1]), "=r"(r[2]), "=r"(r[3]) : "r"(addr));
}
__device__ __forceinline__ void ldm4t(uint32_t r[4], uint32_t addr) {
    asm volatile("ldmatrix.sync.aligned.m8n8.x4.trans.shared.b16 {%0,%1,%2,%3}, [%4];"
                 : "=r"(r[0]), "=r"(r[1]), "=r"(r[2]), "=r"(r[3]) : "r"(addr));
}
__device__ __forceinline__ void mmaf16(float c[4], const uint32_t a[4],
                                       uint32_t b0, uint32_t b1) {
    asm volatile(
        "mma.sync.aligned.m16n8k16.row.col.f32.f16.f16.f32 "
        "{%0,%1,%2,%3},{%4,%5,%6,%7},{%8,%9},{%0,%1,%2,%3};"
        : "+f"(c[0]), "+f"(c[1]), "+f"(c[2]), "+f"(c[3])
        : "r"(a[0]), "r"(a[1]), "r"(a[2]), "r"(a[3]), "r"(b0), "r"(b1));
}
__device__ __forceinline__ void cp16(uint32_t dst, const void* src) {
    asm volatile("cp.async.cg.shared.global [%0], [%1], 16;" :: "r"(dst), "l"(src));
}
#define CP_COMMIT() asm volatile("cp.async.commit_group;" ::: "memory")
#define CP_WAIT0()  asm volatile("cp.async.wait_group 0;" ::: "memory")
// named barrier for one half-CTA (256 threads); id = half+1 (0 reserved)
#define BARH(h) asm volatile("bar.sync %0, %1;" :: "r"((h) + 1), "r"(256) : "memory")

__global__ void prep_kernel(const float* __restrict__ wqkv,
                            const float* __restrict__ wproj) {
    int i = blockIdx.x * blockDim.x + threadIdx.x;   // 0..65535
    int m = i >> 14, n = (i >> 7) & 127, k = i & 127;
    float v = (m < 3) ? wqkv[k * 384 + m * 128 + n] : wproj[k * 128 + n];
    g_wh[m][n * 128 + k] = __float2half_rn(v);
}

__global__ void __launch_bounds__(512, 1)
swin_kernel(const float* __restrict__ x,
            const float* __restrict__ bproj,
            float* __restrict__ out) {
    extern __shared__ char smem[];
    const uint32_t sb = s2u(smem);
    const int tid = threadIdx.x, wid = tid >> 5, lane = tid & 31;
    const int g = lane >> 2, tg = lane & 3;
    const int lg = lane >> 3, lr = lane & 7;
    const int half = wid >> 3, hw = wid & 7, htid = tid & 255;

    // ---- stage all four weights ONCE (resident for the whole kernel) -------
#pragma unroll
    for (int m = 0; m < 4; m++)
#pragma unroll
        for (int i = 0; i < 4; i++) {
            int id = i * 512 + tid;          // 0..2047
            int n = id >> 4, ch = id & 15;
            cp16(sb + m * 32768 + xoff(n, ch), g_wh[m] + n * 128 + ch * 8);
        }
    CP_COMMIT();
    CP_WAIT0();
    __syncthreads();

    const uint32_t xO = HBASE + half * HSTRIDE;   // X -> V
    const uint32_t qO = xO + 16384;               // Q
    const uint32_t kO = xO + 32768;               // K -> O
    const int m0 = (hw >> 2) * 32, n0 = (hw & 3) * 32;   // GEMM warp tile
    const int hd = hw >> 1, hf = hw & 1, rb = hf * 32;   // attention mapping

    for (int w = blockIdx.x * 2 + half; w < 8192; w += WSTRIDE) {
        const int b = w >> 10;
        const int hs0 = ((w >> 5) & 31) * 8 + 4;   // +SS cyclic shift
        const int ws0 = (w & 31) * 8 + 4;
        const float* xb = x + (size_t)b * (128 * 256 * 256);

        // ---- gather shifted window X (fp16) --------------------------------
#pragma unroll 4
        for (int i = 0; i < 16; i++) {
            int idx = i * 256 + htid;          // 4096 (channel-pair, token)
            int c2 = idx >> 6, t = idx & 63;
            int h = (hs0 + (t >> 3)) & 255, wv = (ws0 + (t & 7)) & 255;
            const float* src = xb + (size_t)(2 * c2) * 65536 + h * 256 + wv;
            float v0 = __ldg(src), v1 = __ldg(src + 65536);
            *(__half2*)(smem + xO + xoff(t, c2 >> 2) + (c2 & 3) * 4) =
                __floats2half2_rn(v0, v1);
        }
        BARH(half);   // X visible to all warps of this half

        // ---- fused Q+K GEMM (shared A fragments) ---------------------------
        {
            float aq[2][4][4], ak[2][4][4];
#pragma unroll
            for (int mi = 0; mi < 2; mi++)
#pragma unroll
                for (int nb = 0; nb < 4; nb++)
#pragma unroll
                    for (int j = 0; j < 4; j++) { aq[mi][nb][j] = 0.f; ak[mi][nb][j] = 0.f; }
#pragma unroll
            for (int ks = 0; ks < 8; ks++) {
                uint32_t a[2][4];
#pragma unroll
                for (int mi = 0; mi < 2; mi++)
                    ldm4(a[mi], sb + xO + xoff(m0 + mi * 16 + (lg & 1) * 8 + lr,
                                               ks * 2 + (lg >> 1)));
#pragma unroll
                for (int ni = 0; ni < 2; ni++) {
                    uint32_t bq[4], bk[4];
                    uint32_t bo = xoff(n0 + ni * 16 + (lg >> 1) * 8 + lr,
                                       ks * 2 + (lg & 1));
                    ldm4(bq, sb + WQ_OFF + bo);
                    ldm4(bk, sb + WK_OFF + bo);
#pragma unroll
                    for (int mi = 0; mi < 2; mi++) {
                        mmaf16(aq[mi][2 * ni], a[mi], bq[0], bq[1]);
                        mmaf16(aq[mi][2 * ni + 1], a[mi], bq[2], bq[3]);
                        mmaf16(ak[mi][2 * ni], a[mi], bk[0], bk[1]);
                        mmaf16(ak[mi][2 * ni + 1], a[mi], bk[2], bk[3]);
                    }
                }
            }
            // epilogue: Q (scaled) and K
#pragma unroll
            for (int mi = 0; mi < 2; mi++)
#pragma unroll
                for (int nb = 0; nb < 4; nb++) {
                    int r = m0 + mi * 16 + g;
                    int c = n0 + nb * 8 + 2 * tg;
                    uint32_t o1 = xoff(r, c >> 3) + (c & 7) * 2;
                    uint32_t o2 = xoff(r + 8, c >> 3) + (c & 7) * 2;
                    *(__half2*)(smem + qO + o1) =
                        __floats2half2_rn(aq[mi][nb][0] * SCALE_F, aq[mi][nb][1] * SCALE_F);
                    *(__half2*)(smem + qO + o2) =
                        __floats2half2_rn(aq[mi][nb][2] * SCALE_F, aq[mi][nb][3] * SCALE_F);
                    *(__half2*)(smem + kO + o1) =
                        __floats2half2_rn(ak[mi][nb][0], ak[mi][nb][1]);
                    *(__half2*)(smem + kO + o2) =
                        __floats2half2_rn(ak[mi][nb][2], ak[mi][nb][3]);
                }
        }

        // ---- V GEMM into registers (X still live) --------------------------
        float av[2][4][4];
#pragma unroll
        for (int mi = 0; mi < 2; mi++)
#pragma unroll
            for (int nb = 0; nb < 4; nb++)
#pragma unroll
                for (int j = 0; j < 4; j++) av[mi][nb][j] = 0.f;
#pragma unroll
        for (int ks = 0; ks < 8; ks++) {
            uint32_t a[2][4];
#pragma unroll
            for (int mi = 0; mi < 2; mi++)
                ldm4(a[mi], sb + xO + xoff(m0 + mi * 16 + (lg & 1) * 8 + lr,
                                           ks * 2 + (lg >> 1)));
#pragma unroll
            for (int ni = 0; ni < 2; ni++) {
                uint32_t bf[4];
                ldm4(bf, sb + WV_OFF + xoff(n0 + ni * 16 + (lg >> 1) * 8 + lr,
                                            ks * 2 + (lg & 1)));
#pragma unroll
                for (int mi = 0; mi < 2; mi++) {
                    mmaf16(av[mi][2 * ni], a[mi], bf[0], bf[1]);
                    mmaf16(av[mi][2 * ni + 1], a[mi], bf[2], bf[3]);
                }
            }
        }
        BARH(half);   // all X reads done; Q/K visible

        // ---- store V over X -------------------------------------------------
#pragma unroll
        for (int mi = 0; mi < 2; mi++)
#pragma unroll
            for (int nb = 0; nb < 4; nb++) {
                int r = m0 + mi * 16 + g;
                int c = n0 + nb * 8 + 2 * tg;
                *(__half2*)(smem + xO + xoff(r, c >> 3) + (c & 7) * 2) =
                    __floats2half2_rn(av[mi][nb][0], av[mi][nb][1]);
                *(__half2*)(smem + xO + xoff(r + 8, c >> 3) + (c & 7) * 2) =
                    __floats2half2_rn(av[mi][nb][2], av[mi][nb][3]);
            }

        // ---- S = Q K^T + softmax; P stays in registers ----------------------
        uint32_t ph[2][16];
#pragma unroll
        for (int mi = 0; mi < 2; mi++) {
            float s[8][4];
#pragma unroll
            for (int nb = 0; nb < 8; nb++)
#pragma unroll
                for (int j = 0; j < 4; j++) s[nb][j] = 0.f;
#pragma unroll
            for (int ks = 0; ks < 2; ks++) {
                uint32_t a[4];
                ldm4(a, sb + qO + xoff(rb + mi * 16 + (lg & 1) * 8 + lr,
                                       hd * 4 + ks * 2 + (lg >> 1)));
#pragma unroll
                for (int ni = 0; ni < 4; ni++) {
                    uint32_t bf[4];
                    ldm4(bf, sb + kO + xoff(ni * 16 + (lg >> 1) * 8 + lr,
                                            hd * 4 + ks * 2 + (lg & 1)));
                    mmaf16(s[2 * ni], a, bf[0], bf[1]);
                    mmaf16(s[2 * ni + 1], a, bf[2], bf[3]);
                }
            }
#pragma unroll
            for (int h2 = 0; h2 < 2; h2++) {
                float m = -3.0e38f;
#pragma unroll
                for (int nb = 0; nb < 8; nb++)
                    m = fmaxf(m, fmaxf(s[nb][2 * h2], s[nb][2 * h2 + 1]));
                m = fmaxf(m, __shfl_xor_sync(0xffffffffu, m, 1));
                m = fmaxf(m, __shfl_xor_sync(0xffffffffu, m, 2));
                float e[16], sum = 0.f;
#pragma unroll
                for (int nb = 0; nb < 8; nb++) {
                    float e0 = __expf(s[nb][2 * h2] - m);
                    float e1 = __expf(s[nb][2 * h2 + 1] - m);
                    e[2 * nb] = e0; e[2 * nb + 1] = e1; sum += e0 + e1;
                }
                sum += __shfl_xor_sync(0xffffffffu, sum, 1);
                sum += __shfl_xor_sync(0xffffffffu, sum, 2);
                float inv = 1.f / sum;
#pragma unroll
                for (int nb = 0; nb < 8; nb++) {
                    __half2 hv = __floats2half2_rn(e[2 * nb] * inv, e[2 * nb + 1] * inv);
                    ph[mi][h2 * 8 + nb] = *(uint32_t*)&hv;
                }
            }
        }
        BARH(half);   // V visible; all Q/K reads done (O may overlay K)

        // ---- O = P @ V_head, P-registers feed mma A directly -----------------
#pragma unroll
        for (int mi = 0; mi < 2; mi++) {
            float o[4][4];
#pragma unroll
            for (int nb = 0; nb < 4; nb++)
#pragma unroll
                for (int j = 0; j < 4; j++) o[nb][j] = 0.f;
#pragma unroll
            for (int tk = 0; tk < 4; tk++) {
                uint32_t pa[4];
                pa[0] = ph[mi][2 * tk];
                pa[1] = ph[mi][8 + 2 * tk];
                pa[2] = ph[mi][2 * tk + 1];
                pa[3] = ph[mi][8 + 2 * tk + 1];
#pragma unroll
                for (int dp = 0; dp < 2; dp++) {
                    uint32_t bf[4];
                    ldm4t(bf, sb + xO + xoff(tk * 16 + (lg & 1) * 8 + lr,
                                             hd * 4 + dp * 2 + (lg >> 1)));
                    mmaf16(o[2 * dp], pa, bf[0], bf[1]);
                    mmaf16(o[2 * dp + 1], pa, bf[2], bf[3]);
                }
            }
#pragma unroll
            for (int nb = 0; nb < 4; nb++) {
                int r = rb + mi * 16 + g;
                int c = hd * 32 + nb * 8 + 2 * tg;
                *(__half2*)(smem + kO + xoff(r, c >> 3) + (c & 7) * 2) =
                    __floats2half2_rn(o[nb][0], o[nb][1]);
                *(__half2*)(smem + kO + xoff(r + 8, c >> 3) + (c & 7) * 2) =
                    __floats2half2_rn(o[nb][2], o[nb][3]);
            }
        }
        BARH(half);   // O visible; all V reads done

        // ---- proj: Y = O @ WprojT + bias, direct gmem scatter ---------------
        {
            float acc[2][4][4];
#pragma unroll
            for (int mi = 0; mi < 2; mi++)
#pragma unroll
                for (int nb = 0; nb < 4; nb++)
#pragma unroll
                    for (int j = 0; j < 4; j++) acc[mi][nb][j] = 0.f;
#pragma unroll
            for (int ks = 0; ks < 8; ks++) {
                uint32_t a[2][4];
#pragma unroll
                for (int mi = 0; mi < 2; mi++)
                    ldm4(a[mi], sb + kO + xoff(m0 + mi * 16 + (lg & 1) * 8 + lr,
                                               ks * 2 + (lg >> 1)));
#pragma unroll
                for (int ni = 0; ni < 2; ni++) {
                    uint32_t bf[4];
                    ldm4(bf, sb + WP_OFF + xoff(n0 + ni * 16 + (lg >> 1) * 8 + lr,
                                                ks * 2 + (lg & 1)));
#pragma unroll
                    for (int mi = 0; mi < 2; mi++) {
                        mmaf16(acc[mi][2 * ni], a[mi], bf[0], bf[1]);
                        mmaf16(acc[mi][2 * ni + 1], a[mi], bf[2], bf[3]);
                    }
                }
            }
            float* ob = out + (size_t)b * (128 * 256 * 256);
#pragma unroll
            for (int mi = 0; mi < 2; mi++) {
                int t0 = m0 + mi * 16 + g, t1 = t0 + 8;
                float* o0 = ob + ((hs0 + (t0 >> 3)) & 255) * 256 + ((ws0 + (t0 & 7)) & 255);
                float* o1 = ob + ((hs0 + (t1 >> 3)) & 255) * 256 + ((ws0 + (t1 & 7)) & 255);
#pragma unroll
                for (int nb = 0; nb < 4; nb++) {
                    int c = n0 + nb * 8 + 2 * tg;
                    float b0 = __ldg(bproj + c), b1 = __ldg(bproj + c + 1);
                    o0[(size_t)c * 65536] = acc[mi][nb][0] + b0;
                    o0[(size_t)(c + 1) * 65536] = acc[mi][nb][1] + b1;
                    o1[(size_t)c * 65536] = acc[mi][nb][2] + b0;
                    o1[(size_t)(c + 1) * 65536] = acc[mi][nb][3] + b1;
                }
            }
        }
        BARH(half);   // O reads done -> next window may overwrite X/Q/K
    }
}

extern "C" void kernel_launch(void* const* d_in, const int* in_sizes, int n_in,
                              void* d_out, int out_size) {
    const float* x     = (const float*)d_in[0];
    const float* wqkv  = (const float*)d_in[1];
    const float* wproj = (const float*)d_in[2];
    const float* bproj = (const float*)d_in[3];
    float* out = (float*)d_out;

    prep_kernel<<<256, 256>>>(wqkv, wproj);

    cudaFuncSetAttribute(swin_kernel,
                         cudaFuncAttributeMaxDynamicSharedMemorySize, SMEM_TOTAL);
    swin_kernel<<<NCTA, 512, SMEM_TOTAL>>>(x, bproj, out);
}

// round 13
// speedup vs baseline: 1.1318x; 1.1318x over previous
#include <cuda_runtime.h>
#include <cuda_fp16.h>
#include <cstdint>

// ---------------------------------------------------------------------------
// SwinStyleAttention, fp16 mma.sync, fp32 accumulate.
// B=8, C=128, H=W=256, WS=8, SS=4, HEADS=4, DH=32.
// One CTA = 1 window = 64 tokens. 8192 CTAs, 256 threads, 2 CTAs/SM.
// Phase order: gather -> fused QK -> S/softmax (P in regs, weight staging
// overlapped) -> V (over K) -> PV (O over X) -> proj (direct gmem scatter).
// ---------------------------------------------------------------------------

#define SCALE_F 0.17677669529663687f

#define X_OFF   0          // X -> O (16KB)
#define Q_OFF   16384      // Q (16KB)
#define K_OFF   32768      // K -> V (16KB)
#define W_OFF   49152      // Wq -> Wv (32KB)
#define WB_OFF  81920      // Wk -> Wproj (32KB)
#define SMEM_TOTAL 114688

__device__ __align__(16) __half g_wh[4][16384];   // WqT, WkT, WvT, WprojT

__device__ __forceinline__ uint32_t s2u(const void* p) {
    uint32_t a;
    asm("{ .reg .u64 t; cvta.to.shared.u64 t, %1; cvt.u32.u64 %0, t; }" : "=r"(a) : "l"(p));
    return a;
}
// (row, 16B-chunk) in a 256B-row fp16 tile, XOR-swizzled
__device__ __forceinline__ uint32_t xoff(int row, int chunk) {
    return (uint32_t)(row * 256 + ((chunk ^ (row & 7)) << 4));
}
__device__ __forceinline__ void ldm4(uint32_t r[4], uint32_t addr) {
    asm volatile("ldmatrix.sync.aligned.m8n8.x4.shared.b16 {%0,%1,%2,%3}, [%4];"
                 : "=r"(r[0]), "=r"(r[1]), "=r"(r[2]), "=r"(r[3]) : "r"(addr));
}
__device__ __forceinline__ void ldm4t(uint32_t r[4], uint32_t addr) {
    asm volatile("ldmatrix.sync.aligned.m8n8.x4.trans.shared.b16 {%0,%1,%2,%3}, [%4];"
                 : "=r"(r[0]), "=r"(r[1]), "=r"(r[2]), "=r"(r[3]) : "r"(addr));
}
__device__ __forceinline__ void mmaf16(float c[4], const uint32_t a[4],
                                       uint32_t b0, uint32_t b1) {
    asm volatile(
        "mma.sync.aligned.m16n8k16.row.col.f32.f16.f16.f32 "
        "{%0,%1,%2,%3},{%4,%5,%6,%7},{%8,%9},{%0,%1,%2,%3};"
        : "+f"(c[0]), "+f"(c[1]), "+f"(c[2]), "+f"(c[3])
        : "r"(a[0]), "r"(a[1]), "r"(a[2]), "r"(a[3]), "r"(b0), "r"(b1));
}
__device__ __forceinline__ void cp16(uint32_t dst, const void* src) {
    asm volatile("cp.async.cg.shared.global [%0], [%1], 16;" :: "r"(dst), "l"(src));
}
#define CP_COMMIT() asm volatile("cp.async.commit_group;" ::: "memory")
#define CP_WAIT0()  asm volatile("cp.async.wait_group 0;" ::: "memory")

__device__ __forceinline__ void stageW(uint32_t dstBase, const __half* src, int tid) {
#pragma unroll
    for (int i = 0; i < 8; i++) {
        int id = i * 256 + tid;          // 0..2047
        int n = id >> 4, ch = id & 15;
        cp16(dstBase + xoff(n, ch), src + n * 128 + ch * 8);
    }
    CP_COMMIT();
}

__global__ void prep_kernel(const float* __restrict__ wqkv,
                            const float* __restrict__ wproj) {
    int i = blockIdx.x * blockDim.x + threadIdx.x;   // 0..65535
    int m = i >> 14, n = (i >> 7) & 127, k = i & 127;
    float v = (m < 3) ? wqkv[k * 384 + m * 128 + n] : wproj[k * 128 + n];
    g_wh[m][n * 128 + k] = __float2half_rn(v);
}

__global__ void __launch_bounds__(256, 2)
swin_kernel(const float* __restrict__ x,
            const float* __restrict__ bproj,
            float* __restrict__ out) {
    extern __shared__ char smem[];
    const uint32_t sb = s2u(smem);
    const int tid = threadIdx.x, wid = tid >> 5, lane = tid & 31;
    const int g = lane >> 2, tg = lane & 3;
    const int lg = lane >> 3, lr = lane & 7;

    const int p = blockIdx.x;
    const int b = p >> 10;
    const int hs0 = ((p >> 5) & 31) * 8 + 4;   // +SS cyclic shift
    const int ws0 = (p & 31) * 8 + 4;
    const float* xb = x + (size_t)b * (128 * 256 * 256);

    const int m0 = (wid >> 2) * 32, n0 = (wid & 3) * 32;   // GEMM warp tile
    const int hd = wid >> 1, hf = wid & 1, rb = hf * 32;   // attention mapping

    // ---- stage Wq, Wk; gather shifted window X (fp16) ----------------------
    stageW(sb + W_OFF, g_wh[0], tid);    // Wq
    stageW(sb + WB_OFF, g_wh[1], tid);   // Wk
#pragma unroll 4
    for (int i = 0; i < 16; i++) {
        int idx = i * 256 + tid;         // 4096 (channel-pair, token)
        int c2 = idx >> 6, t = idx & 63;
        int h = (hs0 + (t >> 3)) & 255, wv = (ws0 + (t & 7)) & 255;
        const float* src = xb + (size_t)(2 * c2) * 65536 + h * 256 + wv;
        float v0 = __ldg(src), v1 = __ldg(src + 65536);
        *(__half2*)(smem + X_OFF + xoff(t, c2 >> 2) + (c2 & 3) * 4) =
            __floats2half2_rn(v0, v1);
    }
    CP_WAIT0();
    __syncthreads();                     // (0) X, Wq, Wk visible

    // ---- fused Q+K GEMM (shared A fragments) --------------------------------
    {
        float aq[2][4][4], ak[2][4][4];
#pragma unroll
        for (int mi = 0; mi < 2; mi++)
#pragma unroll
            for (int nb = 0; nb < 4; nb++)
#pragma unroll
                for (int j = 0; j < 4; j++) { aq[mi][nb][j] = 0.f; ak[mi][nb][j] = 0.f; }
#pragma unroll
        for (int ks = 0; ks < 8; ks++) {
            uint32_t a[2][4];
#pragma unroll
            for (int mi = 0; mi < 2; mi++)
                ldm4(a[mi], sb + X_OFF + xoff(m0 + mi * 16 + (lg & 1) * 8 + lr,
                                              ks * 2 + (lg >> 1)));
#pragma unroll
            for (int ni = 0; ni < 2; ni++) {
                uint32_t bq[4], bk[4];
                uint32_t bo = xoff(n0 + ni * 16 + (lg >> 1) * 8 + lr,
                                   ks * 2 + (lg & 1));
                ldm4(bq, sb + W_OFF + bo);
                ldm4(bk, sb + WB_OFF + bo);
#pragma unroll
                for (int mi = 0; mi < 2; mi++) {
                    mmaf16(aq[mi][2 * ni], a[mi], bq[0], bq[1]);
                    mmaf16(aq[mi][2 * ni + 1], a[mi], bq[2], bq[3]);
                    mmaf16(ak[mi][2 * ni], a[mi], bk[0], bk[1]);
                    mmaf16(ak[mi][2 * ni + 1], a[mi], bk[2], bk[3]);
                }
            }
        }
#pragma unroll
        for (int mi = 0; mi < 2; mi++)
#pragma unroll
            for (int nb = 0; nb < 4; nb++) {
                int r = m0 + mi * 16 + g;
                int c = n0 + nb * 8 + 2 * tg;
                uint32_t o1 = xoff(r, c >> 3) + (c & 7) * 2;
                uint32_t o2 = xoff(r + 8, c >> 3) + (c & 7) * 2;
                *(__half2*)(smem + Q_OFF + o1) =
                    __floats2half2_rn(aq[mi][nb][0] * SCALE_F, aq[mi][nb][1] * SCALE_F);
                *(__half2*)(smem + Q_OFF + o2) =
                    __floats2half2_rn(aq[mi][nb][2] * SCALE_F, aq[mi][nb][3] * SCALE_F);
                *(__half2*)(smem + K_OFF + o1) =
                    __floats2half2_rn(ak[mi][nb][0], ak[mi][nb][1]);
                *(__half2*)(smem + K_OFF + o2) =
                    __floats2half2_rn(ak[mi][nb][2], ak[mi][nb][3]);
            }
    }
    __syncthreads();                     // (1) Q,K visible; W,WB free

    // ---- stage Wv, Wproj (async; overlapped by S below) ---------------------
    stageW(sb + W_OFF, g_wh[2], tid);    // Wv
    stageW(sb + WB_OFF, g_wh[3], tid);   // Wproj

    // ---- S = Q K^T + softmax; P stays in registers ---------------------------
    uint32_t ph[2][16];
#pragma unroll
    for (int mi = 0; mi < 2; mi++) {
        float s[8][4];
#pragma unroll
        for (int nb = 0; nb < 8; nb++)
#pragma unroll
            for (int j = 0; j < 4; j++) s[nb][j] = 0.f;
#pragma unroll
        for (int ks = 0; ks < 2; ks++) {
            uint32_t a[4];
            ldm4(a, sb + Q_OFF + xoff(rb + mi * 16 + (lg & 1) * 8 + lr,
                                      hd * 4 + ks * 2 + (lg >> 1)));
#pragma unroll
            for (int ni = 0; ni < 4; ni++) {
                uint32_t bf[4];
                ldm4(bf, sb + K_OFF + xoff(ni * 16 + (lg >> 1) * 8 + lr,
                                           hd * 4 + ks * 2 + (lg & 1)));
                mmaf16(s[2 * ni], a, bf[0], bf[1]);
                mmaf16(s[2 * ni + 1], a, bf[2], bf[3]);
            }
        }
#pragma unroll
        for (int h2 = 0; h2 < 2; h2++) {
            float m = -3.0e38f;
#pragma unroll
            for (int nb = 0; nb < 8; nb++)
                m = fmaxf(m, fmaxf(s[nb][2 * h2], s[nb][2 * h2 + 1]));
            m = fmaxf(m, __shfl_xor_sync(0xffffffffu, m, 1));
            m = fmaxf(m, __shfl_xor_sync(0xffffffffu, m, 2));
            float e[16], sum = 0.f;
#pragma unroll
            for (int nb = 0; nb < 8; nb++) {
                float e0 = __expf(s[nb][2 * h2] - m);
                float e1 = __expf(s[nb][2 * h2 + 1] - m);
                e[2 * nb] = e0; e[2 * nb + 1] = e1; sum += e0 + e1;
            }
            sum += __shfl_xor_sync(0xffffffffu, sum, 1);
            sum += __shfl_xor_sync(0xffffffffu, sum, 2);
            float inv = 1.f / sum;
#pragma unroll
            for (int nb = 0; nb < 8; nb++) {
                __half2 hv = __floats2half2_rn(e[2 * nb] * inv, e[2 * nb + 1] * inv);
                ph[mi][h2 * 8 + nb] = *(uint32_t*)&hv;
            }
        }
    }
    CP_WAIT0();
    __syncthreads();                     // (2) all S reads done; Wv,Wproj visible

    // ---- V GEMM (X @ Wv) -> store V over K (K dead) --------------------------
    {
        float av[2][4][4];
#pragma unroll
        for (int mi = 0; mi < 2; mi++)
#pragma unroll
            for (int nb = 0; nb < 4; nb++)
#pragma unroll
                for (int j = 0; j < 4; j++) av[mi][nb][j] = 0.f;
#pragma unroll
        for (int ks = 0; ks < 8; ks++) {
            uint32_t a[2][4];
#pragma unroll
            for (int mi = 0; mi < 2; mi++)
                ldm4(a[mi], sb + X_OFF + xoff(m0 + mi * 16 + (lg & 1) * 8 + lr,
                                              ks * 2 + (lg >> 1)));
#pragma unroll
            for (int ni = 0; ni < 2; ni++) {
                uint32_t bf[4];
                ldm4(bf, sb + W_OFF + xoff(n0 + ni * 16 + (lg >> 1) * 8 + lr,
                                           ks * 2 + (lg & 1)));
#pragma unroll
                for (int mi = 0; mi < 2; mi++) {
                    mmaf16(av[mi][2 * ni], a[mi], bf[0], bf[1]);
                    mmaf16(av[mi][2 * ni + 1], a[mi], bf[2], bf[3]);
                }
            }
        }
#pragma unroll
        for (int mi = 0; mi < 2; mi++)
#pragma unroll
            for (int nb = 0; nb < 4; nb++) {
                int r = m0 + mi * 16 + g;
                int c = n0 + nb * 8 + 2 * tg;
                *(__half2*)(smem + K_OFF + xoff(r, c >> 3) + (c & 7) * 2) =
                    __floats2half2_rn(av[mi][nb][0], av[mi][nb][1]);
                *(__half2*)(smem + K_OFF + xoff(r + 8, c >> 3) + (c & 7) * 2) =
                    __floats2half2_rn(av[mi][nb][2], av[mi][nb][3]);
            }
    }
    __syncthreads();                     // (3) V visible; X reads done

    // ---- O = P @ V_head -> store O over X (X dead) ---------------------------
#pragma unroll
    for (int mi = 0; mi < 2; mi++) {
        float o[4][4];
#pragma unroll
        for (int nb = 0; nb < 4; nb++)
#pragma unroll
            for (int j = 0; j < 4; j++) o[nb][j] = 0.f;
#pragma unroll
        for (int tk = 0; tk < 4; tk++) {
            uint32_t pa[4];
            pa[0] = ph[mi][2 * tk];
            pa[1] = ph[mi][8 + 2 * tk];
            pa[2] = ph[mi][2 * tk + 1];
            pa[3] = ph[mi][8 + 2 * tk + 1];
#pragma unroll
            for (int dp = 0; dp < 2; dp++) {
                uint32_t bf[4];
                ldm4t(bf, sb + K_OFF + xoff(tk * 16 + (lg & 1) * 8 + lr,
                                            hd * 4 + dp * 2 + (lg >> 1)));
                mmaf16(o[2 * dp], pa, bf[0], bf[1]);
                mmaf16(o[2 * dp + 1], pa, bf[2], bf[3]);
            }
        }
#pragma unroll
        for (int nb = 0; nb < 4; nb++) {
            int r = rb + mi * 16 + g;
            int c = hd * 32 + nb * 8 + 2 * tg;
            *(__half2*)(smem + X_OFF + xoff(r, c >> 3) + (c & 7) * 2) =
                __floats2half2_rn(o[nb][0], o[nb][1]);
            *(__half2*)(smem + X_OFF + xoff(r + 8, c >> 3) + (c & 7) * 2) =
                __floats2half2_rn(o[nb][2], o[nb][3]);
        }
    }
    __syncthreads();                     // (4) O visible

    // ---- proj: Y = O @ WprojT + bias, direct gmem scatter --------------------
    {
        float acc[2][4][4];
#pragma unroll
        for (int mi = 0; mi < 2; mi++)
#pragma unroll
            for (int nb = 0; nb < 4; nb++)
#pragma unroll
                for (int j = 0; j < 4; j++) acc[mi][nb][j] = 0.f;
#pragma unroll
        for (int ks = 0; ks < 8; ks++) {
            uint32_t a[2][4];
#pragma unroll
            for (int mi = 0; mi < 2; mi++)
                ldm4(a[mi], sb + X_OFF + xoff(m0 + mi * 16 + (lg & 1) * 8 + lr,
                                              ks * 2 + (lg >> 1)));
#pragma unroll
            for (int ni = 0; ni < 2; ni++) {
                uint32_t bf[4];
                ldm4(bf, sb + WB_OFF + xoff(n0 + ni * 16 + (lg >> 1) * 8 + lr,
                                            ks * 2 + (lg & 1)));
#pragma unroll
                for (int mi = 0; mi < 2; mi++) {
                    mmaf16(acc[mi][2 * ni], a[mi], bf[0], bf[1]);
                    mmaf16(acc[mi][2 * ni + 1], a[mi], bf[2], bf[3]);
                }
            }
        }
        float* ob = out + (size_t)b * (128 * 256 * 256);
#pragma unroll
        for (int mi = 0; mi < 2; mi++) {
            int t0 = m0 + mi * 16 + g, t1 = t0 + 8;
            float* o0 = ob + ((hs0 + (t0 >> 3)) & 255) * 256 + ((ws0 + (t0 & 7)) & 255);
            float* o1 = ob + ((hs0 + (t1 >> 3)) & 255) * 256 + ((ws0 + (t1 & 7)) & 255);
#pragma unroll
            for (int nb = 0; nb < 4; nb++) {
                int c = n0 + nb * 8 + 2 * tg;
                float b0 = __ldg(bproj + c), b1 = __ldg(bproj + c + 1);
                o0[(size_t)c * 65536] = acc[mi][nb][0] + b0;
                o0[(size_t)(c + 1) * 65536] = acc[mi][nb][1] + b1;
                o1[(size_t)c * 65536] = acc[mi][nb][2] + b0;
                o1[(size_t)(c + 1) * 65536] = acc[mi][nb][3] + b1;
            }
        }
    }
}

extern "C" void kernel_launch(void* const* d_in, const int* in_sizes, int n_in,
                              void* d_out, int out_size) {
    const float* x     = (const float*)d_in[0];
    const float* wqkv  = (const float*)d_in[1];
    const float* wproj = (const float*)d_in[2];
    const float* bproj = (const float*)d_in[3];
    float* out = (float*)d_out;

    prep_kernel<<<256, 256>>>(wqkv, wproj);

    cudaFuncSetAttribute(swin_kernel,
                         cudaFuncAttributeMaxDynamicSharedMemorySize, SMEM_TOTAL);
    swin_kernel<<<8192, 256, SMEM_TOTAL>>>(x, bproj, out);
}

// round 15
// speedup vs baseline: 1.2766x; 1.1280x over previous
#include <cuda_runtime.h>
#include <cuda_fp16.h>
#include <cstdint>

// ---------------------------------------------------------------------------
// SwinStyleAttention, fp16 mma.sync, fp32 accumulate.
// B=8, C=128, H=W=256, WS=8, SS=4, HEADS=4, DH=32.
// One CTA = 1 window = 64 tokens. 8192 CTAs, 256 threads, 2 CTAs/SM.
// Q lives only in registers (QK C-frags repacked as S A-frags); P in registers.
// ---------------------------------------------------------------------------

#define SCALE_F 0.17677669529663687f

#define X_OFF   0          // X -> O (16KB)
#define K_OFF   16384      // K -> V (16KB)
#define W_OFF   32768      // Wq -> Wv (32KB)
#define WB_OFF  65536      // Wk -> Wproj (32KB)
#define SMEM_TOTAL 98304

__device__ __align__(16) __half g_wh[4][16384];   // WqT, WkT, WvT, WprojT

__device__ __forceinline__ uint32_t s2u(const void* p) {
    uint32_t a;
    asm("{ .reg .u64 t; cvta.to.shared.u64 t, %1; cvt.u32.u64 %0, t; }" : "=r"(a) : "l"(p));
    return a;
}
// (row, 16B-chunk) in a 256B-row fp16 tile, XOR-swizzled
__device__ __forceinline__ uint32_t xoff(int row, int chunk) {
    return (uint32_t)(row * 256 + ((chunk ^ (row & 7)) << 4));
}
__device__ __forceinline__ void ldm4(uint32_t r[4], uint32_t addr) {
    asm volatile("ldmatrix.sync.aligned.m8n8.x4.shared.b16 {%0,%1,%2,%3}, [%4];"
                 : "=r"(r[0]), "=r"(r[1]), "=r"(r[2]), "=r"(r[3]) : "r"(addr));
}
__device__ __forceinline__ void ldm4t(uint32_t r[4], uint32_t addr) {
    asm volatile("ldmatrix.sync.aligned.m8n8.x4.trans.shared.b16 {%0,%1,%2,%3}, [%4];"
                 : "=r"(r[0]), "=r"(r[1]), "=r"(r[2]), "=r"(r[3]) : "r"(addr));
}
__device__ __forceinline__ void mmaf16(float c[4], const uint32_t a[4],
                                       uint32_t b0, uint32_t b1) {
    asm volatile(
        "mma.sync.aligned.m16n8k16.row.col.f32.f16.f16.f32 "
        "{%0,%1,%2,%3},{%4,%5,%6,%7},{%8,%9},{%0,%1,%2,%3};"
        : "+f"(c[0]), "+f"(c[1]), "+f"(c[2]), "+f"(c[3])
        : "r"(a[0]), "r"(a[1]), "r"(a[2]), "r"(a[3]), "r"(b0), "r"(b1));
}
__device__ __forceinline__ void cp16(uint32_t dst, const void* src) {
    asm volatile("cp.async.cg.shared.global [%0], [%1], 16;" :: "r"(dst), "l"(src));
}
#define CP_COMMIT() asm volatile("cp.async.commit_group;" ::: "memory")
#define CP_WAIT0()  asm volatile("cp.async.wait_group 0;" ::: "memory")

__device__ __forceinline__ uint32_t packh2(float a, float b) {
    __half2 h = __floats2half2_rn(a, b);
    return *(uint32_t*)&h;
}

__device__ __forceinline__ void stageW(uint32_t dstBase, const __half* src, int tid) {
#pragma unroll
    for (int i = 0; i < 8; i++) {
        int id = i * 256 + tid;          // 0..2047
        int n = id >> 4, ch = id & 15;
        cp16(dstBase + xoff(n, ch), src + n * 128 + ch * 8);
    }
    CP_COMMIT();
}

__global__ void prep_kernel(const float* __restrict__ wqkv,
                            const float* __restrict__ wproj) {
    int i = blockIdx.x * blockDim.x + threadIdx.x;   // 0..65535
    int m = i >> 14, n = (i >> 7) & 127, k = i & 127;
    float v = (m < 3) ? wqkv[k * 384 + m * 128 + n] : wproj[k * 128 + n];
    g_wh[m][n * 128 + k] = __float2half_rn(v);
}

__global__ void __launch_bounds__(256, 2)
swin_kernel(const float* __restrict__ x,
            const float* __restrict__ bproj,
            float* __restrict__ out) {
    extern __shared__ char smem[];
    const uint32_t sb = s2u(smem);
    const int tid = threadIdx.x, wid = tid >> 5, lane = tid & 31;
    const int g = lane >> 2, tg = lane & 3;
    const int lg = lane >> 3, lr = lane & 7;

    const int p = blockIdx.x;
    const int b = p >> 10;
    const int hs0 = ((p >> 5) & 31) * 8 + 4;   // +SS cyclic shift
    const int ws0 = (p & 31) * 8 + 4;
    const float* xb = x + (size_t)b * (128 * 256 * 256);

    // warp mapping: rows hf*32, cols/head hd*32 — SAME tile in QK-GEMM and S.
    const int hf = wid >> 2, hd = wid & 3;
    const int rb = hf * 32, cb = hd * 32;

    // ---- P0: stage Wq, Wk; gather shifted window X (fp16) ------------------
    stageW(sb + W_OFF, g_wh[0], tid);    // Wq
    stageW(sb + WB_OFF, g_wh[1], tid);   // Wk
#pragma unroll 4
    for (int i = 0; i < 16; i++) {
        int idx = i * 256 + tid;         // 4096 (channel-pair, token)
        int c2 = idx >> 6, t = idx & 63;
        int h = (hs0 + (t >> 3)) & 255, wv = (ws0 + (t & 7)) & 255;
        const float* src = xb + (size_t)(2 * c2) * 65536 + h * 256 + wv;
        float v0 = __ldg(src), v1 = __ldg(src + 65536);
        *(__half2*)(smem + X_OFF + xoff(t, c2 >> 2) + (c2 & 3) * 4) =
            __floats2half2_rn(v0, v1);
    }
    CP_WAIT0();
    __syncthreads();                     // (A) X, Wq, Wk visible

    // ---- P1: fused Q+K GEMM; Q stays in registers as S A-fragments ----------
    uint32_t qa[2][2][4];                // [mi][kappa][a0..a3]
    {
        float aq[2][4][4], ak[2][4][4];
#pragma unroll
        for (int mi = 0; mi < 2; mi++)
#pragma unroll
            for (int nb = 0; nb < 4; nb++)
#pragma unroll
                for (int j = 0; j < 4; j++) { aq[mi][nb][j] = 0.f; ak[mi][nb][j] = 0.f; }
#pragma unroll
        for (int ks = 0; ks < 8; ks++) {
            uint32_t a[2][4];
#pragma unroll
            for (int mi = 0; mi < 2; mi++)
                ldm4(a[mi], sb + X_OFF + xoff(rb + mi * 16 + (lg & 1) * 8 + lr,
                                              ks * 2 + (lg >> 1)));
#pragma unroll
            for (int ni = 0; ni < 2; ni++) {
                uint32_t bq[4], bk[4];
                uint32_t bo = xoff(cb + ni * 16 + (lg >> 1) * 8 + lr,
                                   ks * 2 + (lg & 1));
                ldm4(bq, sb + W_OFF + bo);
                ldm4(bk, sb + WB_OFF + bo);
#pragma unroll
                for (int mi = 0; mi < 2; mi++) {
                    mmaf16(aq[mi][2 * ni], a[mi], bq[0], bq[1]);
                    mmaf16(aq[mi][2 * ni + 1], a[mi], bq[2], bq[3]);
                    mmaf16(ak[mi][2 * ni], a[mi], bk[0], bk[1]);
                    mmaf16(ak[mi][2 * ni + 1], a[mi], bk[2], bk[3]);
                }
            }
        }
        // Q: scale + pack C-frags -> A-frags (registers only)
#pragma unroll
        for (int mi = 0; mi < 2; mi++)
#pragma unroll
            for (int kk = 0; kk < 2; kk++) {
                qa[mi][kk][0] = packh2(aq[mi][2 * kk][0] * SCALE_F, aq[mi][2 * kk][1] * SCALE_F);
                qa[mi][kk][1] = packh2(aq[mi][2 * kk][2] * SCALE_F, aq[mi][2 * kk][3] * SCALE_F);
                qa[mi][kk][2] = packh2(aq[mi][2 * kk + 1][0] * SCALE_F, aq[mi][2 * kk + 1][1] * SCALE_F);
                qa[mi][kk][3] = packh2(aq[mi][2 * kk + 1][2] * SCALE_F, aq[mi][2 * kk + 1][3] * SCALE_F);
            }
        // K -> smem
#pragma unroll
        for (int mi = 0; mi < 2; mi++)
#pragma unroll
            for (int nb = 0; nb < 4; nb++) {
                int r = rb + mi * 16 + g;
                int c = cb + nb * 8 + 2 * tg;
                *(__half2*)(smem + K_OFF + xoff(r, c >> 3) + (c & 7) * 2) =
                    __floats2half2_rn(ak[mi][nb][0], ak[mi][nb][1]);
                *(__half2*)(smem + K_OFF + xoff(r + 8, c >> 3) + (c & 7) * 2) =
                    __floats2half2_rn(ak[mi][nb][2], ak[mi][nb][3]);
            }
    }
    __syncthreads();                     // (B) K visible; W, WB free

    // ---- P2: stage Wv, Wproj (async; overlapped by S below) -----------------
    stageW(sb + W_OFF, g_wh[2], tid);    // Wv
    stageW(sb + WB_OFF, g_wh[3], tid);   // Wproj

    // ---- P3: S = Q K^T + softmax; P stays in registers -----------------------
    uint32_t ph[2][16];
    {
        uint32_t bK[8][4];               // K B-frags hoisted (shared across mi)
#pragma unroll
        for (int kk = 0; kk < 2; kk++)
#pragma unroll
            for (int ni = 0; ni < 4; ni++)
                ldm4(bK[kk * 4 + ni],
                     sb + K_OFF + xoff(ni * 16 + (lg >> 1) * 8 + lr,
                                       hd * 4 + kk * 2 + (lg & 1)));
#pragma unroll
        for (int mi = 0; mi < 2; mi++) {
            float s[8][4];
#pragma unroll
            for (int nb = 0; nb < 8; nb++)
#pragma unroll
                for (int j = 0; j < 4; j++) s[nb][j] = 0.f;
#pragma unroll
            for (int kk = 0; kk < 2; kk++)
#pragma unroll
                for (int ni = 0; ni < 4; ni++) {
                    mmaf16(s[2 * ni], qa[mi][kk], bK[kk * 4 + ni][0], bK[kk * 4 + ni][1]);
                    mmaf16(s[2 * ni + 1], qa[mi][kk], bK[kk * 4 + ni][2], bK[kk * 4 + ni][3]);
                }
#pragma unroll
            for (int h2 = 0; h2 < 2; h2++) {
                float m = -3.0e38f;
#pragma unroll
                for (int nb = 0; nb < 8; nb++)
                    m = fmaxf(m, fmaxf(s[nb][2 * h2], s[nb][2 * h2 + 1]));
                m = fmaxf(m, __shfl_xor_sync(0xffffffffu, m, 1));
                m = fmaxf(m, __shfl_xor_sync(0xffffffffu, m, 2));
                float e[16], sum = 0.f;
#pragma unroll
                for (int nb = 0; nb < 8; nb++) {
                    float e0 = __expf(s[nb][2 * h2] - m);
                    float e1 = __expf(s[nb][2 * h2 + 1] - m);
                    e[2 * nb] = e0; e[2 * nb + 1] = e1; sum += e0 + e1;
                }
                sum += __shfl_xor_sync(0xffffffffu, sum, 1);
                sum += __shfl_xor_sync(0xffffffffu, sum, 2);
                float inv = 1.f / sum;
#pragma unroll
                for (int nb = 0; nb < 8; nb++)
                    ph[mi][h2 * 8 + nb] = packh2(e[2 * nb] * inv, e[2 * nb + 1] * inv);
            }
        }
    }
    CP_WAIT0();
    __syncthreads();                     // (C) all S reads done; Wv, Wproj visible

    // ---- P4: V GEMM (X @ Wv), 8 warps 32x32 -> store V over K ----------------
    {
        const int m0 = hf * 32, n0 = hd * 32;
        float av[2][4][4];
#pragma unroll
        for (int mi = 0; mi < 2; mi++)
#pragma unroll
            for (int nb = 0; nb < 4; nb++)
#pragma unroll
                for (int j = 0; j < 4; j++) av[mi][nb][j] = 0.f;
#pragma unroll
        for (int ks = 0; ks < 8; ks++) {
            uint32_t a[2][4];
#pragma unroll
            for (int mi = 0; mi < 2; mi++)
                ldm4(a[mi], sb + X_OFF + xoff(m0 + mi * 16 + (lg & 1) * 8 + lr,
                                              ks * 2 + (lg >> 1)));
#pragma unroll
            for (int ni = 0; ni < 2; ni++) {
                uint32_t bf[4];
                ldm4(bf, sb + W_OFF + xoff(n0 + ni * 16 + (lg >> 1) * 8 + lr,
                                           ks * 2 + (lg & 1)));
#pragma unroll
                for (int mi = 0; mi < 2; mi++) {
                    mmaf16(av[mi][2 * ni], a[mi], bf[0], bf[1]);
                    mmaf16(av[mi][2 * ni + 1], a[mi], bf[2], bf[3]);
                }
            }
        }
#pragma unroll
        for (int mi = 0; mi < 2; mi++)
#pragma unroll
            for (int nb = 0; nb < 4; nb++) {
                int r = m0 + mi * 16 + g;
                int c = n0 + nb * 8 + 2 * tg;
                *(__half2*)(smem + K_OFF + xoff(r, c >> 3) + (c & 7) * 2) =
                    __floats2half2_rn(av[mi][nb][0], av[mi][nb][1]);
                *(__half2*)(smem + K_OFF + xoff(r + 8, c >> 3) + (c & 7) * 2) =
                    __floats2half2_rn(av[mi][nb][2], av[mi][nb][3]);
            }
    }
    __syncthreads();                     // (D) V visible; X reads done

    // ---- P5: O = P @ V_head (B hoisted) -> store O over X ---------------------
    {
        uint32_t bV[8][4];
#pragma unroll
        for (int tk = 0; tk < 4; tk++)
#pragma unroll
            for (int dp = 0; dp < 2; dp++)
                ldm4t(bV[tk * 2 + dp],
                      sb + K_OFF + xoff(tk * 16 + (lg & 1) * 8 + lr,
                                        hd * 4 + dp * 2 + (lg >> 1)));
#pragma unroll
        for (int mi = 0; mi < 2; mi++) {
            float o[4][4];
#pragma unroll
            for (int nb = 0; nb < 4; nb++)
#pragma unroll
                for (int j = 0; j < 4; j++) o[nb][j] = 0.f;
#pragma unroll
            for (int tk = 0; tk < 4; tk++) {
                uint32_t pa[4];
                pa[0] = ph[mi][2 * tk];
                pa[1] = ph[mi][8 + 2 * tk];
                pa[2] = ph[mi][2 * tk + 1];
                pa[3] = ph[mi][8 + 2 * tk + 1];
#pragma unroll
                for (int dp = 0; dp < 2; dp++) {
                    mmaf16(o[2 * dp], pa, bV[tk * 2 + dp][0], bV[tk * 2 + dp][1]);
                    mmaf16(o[2 * dp + 1], pa, bV[tk * 2 + dp][2], bV[tk * 2 + dp][3]);
                }
            }
#pragma unroll
            for (int nb = 0; nb < 4; nb++) {
                int r = rb + mi * 16 + g;
                int c = hd * 32 + nb * 8 + 2 * tg;
                *(__half2*)(smem + X_OFF + xoff(r, c >> 3) + (c & 7) * 2) =
                    __floats2half2_rn(o[nb][0], o[nb][1]);
                *(__half2*)(smem + X_OFF + xoff(r + 8, c >> 3) + (c & 7) * 2) =
                    __floats2half2_rn(o[nb][2], o[nb][3]);
            }
        }
    }
    __syncthreads();                     // (E) O visible

    // ---- P6: proj on warps 0-3, 64x32 tiles, direct gmem scatter --------------
    if (wid < 4) {
        const int n0 = wid * 32;
        float acc[4][4][4];
#pragma unroll
        for (int mi = 0; mi < 4; mi++)
#pragma unroll
            for (int nb = 0; nb < 4; nb++)
#pragma unroll
                for (int j = 0; j < 4; j++) acc[mi][nb][j] = 0.f;
#pragma unroll
        for (int ks = 0; ks < 8; ks++) {
            uint32_t a[4][4];
#pragma unroll
            for (int mi = 0; mi < 4; mi++)
                ldm4(a[mi], sb + X_OFF + xoff(mi * 16 + (lg & 1) * 8 + lr,
                                              ks * 2 + (lg >> 1)));
#pragma unroll
            for (int ni = 0; ni < 2; ni++) {
                uint32_t bf[4];
                ldm4(bf, sb + WB_OFF + xoff(n0 + ni * 16 + (lg >> 1) * 8 + lr,
                                            ks * 2 + (lg & 1)));
#pragma unroll
                for (int mi = 0; mi < 4; mi++) {
                    mmaf16(acc[mi][2 * ni], a[mi], bf[0], bf[1]);
                    mmaf16(acc[mi][2 * ni + 1], a[mi], bf[2], bf[3]);
                }
            }
        }
        float* ob = out + (size_t)b * (128 * 256 * 256);
#pragma unroll
        for (int mi = 0; mi < 4; mi++) {
            int t0 = mi * 16 + g, t1 = t0 + 8;
            float* o0 = ob + ((hs0 + (t0 >> 3)) & 255) * 256 + ((ws0 + (t0 & 7)) & 255);
            float* o1 = ob + ((hs0 + (t1 >> 3)) & 255) * 256 + ((ws0 + (t1 & 7)) & 255);
#pragma unroll
            for (int nb = 0; nb < 4; nb++) {
                int c = n0 + nb * 8 + 2 * tg;
                float b0 = __ldg(bproj + c), b1 = __ldg(bproj + c + 1);
                o0[(size_t)c * 65536] = acc[mi][nb][0] + b0;
                o0[(size_t)(c + 1) * 65536] = acc[mi][nb][1] + b1;
                o1[(size_t)c * 65536] = acc[mi][nb][2] + b0;
                o1[(size_t)(c + 1) * 65536] = acc[mi][nb][3] + b1;
            }
        }
    }
}

extern "C" void kernel_launch(void* const* d_in, const int* in_sizes, int n_in,
                              void* d_out, int out_size) {
    const float* x     = (const float*)d_in[0];
    const float* wqkv  = (const float*)d_in[1];
    const float* wproj = (const float*)d_in[2];
    const float* bproj = (const float*)d_in[3];
    float* out = (float*)d_out;

    prep_kernel<<<256, 256>>>(wqkv, wproj);

    cudaFuncSetAttribute(swin_kernel,
                         cudaFuncAttributeMaxDynamicSharedMemorySize, SMEM_TOTAL);
    swin_kernel<<<8192, 256, SMEM_TOTAL>>>(x, bproj, out);
}